// round 1
// baseline (speedup 1.0000x reference)
#include <cuda_runtime.h>

#define NUSER 50000
#define NITEM 50000
#define NEDGE 1600000
#define D 64

// Scratch (device globals — no allocation allowed).
__device__ float g_Wh_rate[NUSER * D];   // user_feat @ W_rate + b_rate
__device__ float g_Wh_rev [NITEM * D];   // item_feat @ W_rev  + b_rev
__device__ float g_cnt_user[NUSER];
__device__ float g_cnt_item[NITEM];

// ---------------------------------------------------------------------------
// Zero d_out (used as the segment-sum accumulator) and the degree counters.
// ---------------------------------------------------------------------------
__global__ void zero_kernel(float4* __restrict__ out, int n4) {
    int i = blockIdx.x * blockDim.x + threadIdx.x;
    if (i < n4) out[i] = make_float4(0.f, 0.f, 0.f, 0.f);
    if (i < NUSER) g_cnt_user[i] = 0.f;
    if (i < NITEM) g_cnt_item[i] = 0.f;
}

// ---------------------------------------------------------------------------
// C[N,64] = A[N,64] @ W[64,64] + b.  64-row tile per 256-thread block,
// 4x4 register blocking (16 FFMA per 1 LDS.128 + 4 LDS.32).
// ---------------------------------------------------------------------------
__global__ void gemm64_kernel(const float* __restrict__ A, const float* __restrict__ W,
                              const float* __restrict__ b, float* __restrict__ C, int N) {
    __shared__ float As[64][68];
    __shared__ float Ws[64][68];
    __shared__ float bs[64];
    const int tid = threadIdx.x;
    const int tx = tid & 15, ty = tid >> 4;
    const int row0 = blockIdx.x * 64;

    if (tid < 64) bs[tid] = b[tid];
    #pragma unroll
    for (int i = tid; i < 1024; i += 256) {
        int k = i >> 4, c4 = (i & 15) << 2;
        float4 w = *reinterpret_cast<const float4*>(W + k * 64 + c4);
        Ws[k][c4] = w.x; Ws[k][c4 + 1] = w.y; Ws[k][c4 + 2] = w.z; Ws[k][c4 + 3] = w.w;
    }
    #pragma unroll
    for (int i = tid; i < 1024; i += 256) {
        int r = i >> 4, k4 = (i & 15) << 2;
        int gr = row0 + r;
        float4 a = (gr < N) ? *reinterpret_cast<const float4*>(A + (size_t)gr * D + k4)
                            : make_float4(0.f, 0.f, 0.f, 0.f);
        As[r][k4] = a.x; As[r][k4 + 1] = a.y; As[r][k4 + 2] = a.z; As[r][k4 + 3] = a.w;
    }
    __syncthreads();

    float4 acc[4];
    {
        float4 bv = make_float4(bs[tx * 4], bs[tx * 4 + 1], bs[tx * 4 + 2], bs[tx * 4 + 3]);
        #pragma unroll
        for (int i = 0; i < 4; i++) acc[i] = bv;
    }
    const int rb = ty * 4;
    #pragma unroll
    for (int k = 0; k < 64; k++) {
        float4 wv = *reinterpret_cast<const float4*>(&Ws[k][tx * 4]);
        float a0 = As[rb + 0][k], a1 = As[rb + 1][k], a2 = As[rb + 2][k], a3 = As[rb + 3][k];
        acc[0].x += a0 * wv.x; acc[0].y += a0 * wv.y; acc[0].z += a0 * wv.z; acc[0].w += a0 * wv.w;
        acc[1].x += a1 * wv.x; acc[1].y += a1 * wv.y; acc[1].z += a1 * wv.z; acc[1].w += a1 * wv.w;
        acc[2].x += a2 * wv.x; acc[2].y += a2 * wv.y; acc[2].z += a2 * wv.z; acc[2].w += a2 * wv.w;
        acc[3].x += a3 * wv.x; acc[3].y += a3 * wv.y; acc[3].z += a3 * wv.z; acc[3].w += a3 * wv.w;
    }
    #pragma unroll
    for (int i = 0; i < 4; i++) {
        int gr = row0 + rb + i;
        if (gr < N)
            *reinterpret_cast<float4*>(C + (size_t)gr * D + tx * 4) = acc[i];
    }
}

// ---------------------------------------------------------------------------
// Edge scatter: 16 threads per edge, each handles one float4 of the 64-wide
// message. Gather hits L2 (Wh is 12.8MB), atomic adds stay in L2.
// red.global.add.v4.f32 quarters atomic instruction count.
// ---------------------------------------------------------------------------
__global__ void scatter_kernel(const float* __restrict__ Wh, const int* __restrict__ src,
                               const int* __restrict__ dst, float* __restrict__ sum,
                               float* __restrict__ cnt, int nedge) {
    int t = blockIdx.x * blockDim.x + threadIdx.x;
    int e = t >> 4;
    if (e >= nedge) return;
    int lane = t & 15;
    int s = __ldg(src + e);
    int d = __ldg(dst + e);
    float4 v = *reinterpret_cast<const float4*>(Wh + (size_t)s * D + lane * 4);
    float* p = sum + (size_t)d * D + lane * 4;
    asm volatile("red.global.add.v4.f32 [%0], {%1, %2, %3, %4};"
                 :: "l"(p), "f"(v.x), "f"(v.y), "f"(v.z), "f"(v.w) : "memory");
    if (lane == 0) atomicAdd(cnt + d, 1.0f);
}

// ---------------------------------------------------------------------------
// Finalize: out = sum/max(cnt,1) + A @ W_loop + h_bias  (fused GEMM+epilogue)
// ---------------------------------------------------------------------------
__global__ void finalize_kernel(const float* __restrict__ A, const float* __restrict__ W,
                                const float* __restrict__ hb, const float* __restrict__ cnt,
                                float* __restrict__ out, int N) {
    __shared__ float As[64][68];
    __shared__ float Ws[64][68];
    __shared__ float bs[64];
    const int tid = threadIdx.x;
    const int tx = tid & 15, ty = tid >> 4;
    const int row0 = blockIdx.x * 64;

    if (tid < 64) bs[tid] = hb[tid];
    #pragma unroll
    for (int i = tid; i < 1024; i += 256) {
        int k = i >> 4, c4 = (i & 15) << 2;
        float4 w = *reinterpret_cast<const float4*>(W + k * 64 + c4);
        Ws[k][c4] = w.x; Ws[k][c4 + 1] = w.y; Ws[k][c4 + 2] = w.z; Ws[k][c4 + 3] = w.w;
    }
    #pragma unroll
    for (int i = tid; i < 1024; i += 256) {
        int r = i >> 4, k4 = (i & 15) << 2;
        int gr = row0 + r;
        float4 a = (gr < N) ? *reinterpret_cast<const float4*>(A + (size_t)gr * D + k4)
                            : make_float4(0.f, 0.f, 0.f, 0.f);
        As[r][k4] = a.x; As[r][k4 + 1] = a.y; As[r][k4 + 2] = a.z; As[r][k4 + 3] = a.w;
    }
    __syncthreads();

    float4 acc[4];
    {
        float4 bv = make_float4(bs[tx * 4], bs[tx * 4 + 1], bs[tx * 4 + 2], bs[tx * 4 + 3]);
        #pragma unroll
        for (int i = 0; i < 4; i++) acc[i] = bv;
    }
    const int rb = ty * 4;
    #pragma unroll
    for (int k = 0; k < 64; k++) {
        float4 wv = *reinterpret_cast<const float4*>(&Ws[k][tx * 4]);
        float a0 = As[rb + 0][k], a1 = As[rb + 1][k], a2 = As[rb + 2][k], a3 = As[rb + 3][k];
        acc[0].x += a0 * wv.x; acc[0].y += a0 * wv.y; acc[0].z += a0 * wv.z; acc[0].w += a0 * wv.w;
        acc[1].x += a1 * wv.x; acc[1].y += a1 * wv.y; acc[1].z += a1 * wv.z; acc[1].w += a1 * wv.w;
        acc[2].x += a2 * wv.x; acc[2].y += a2 * wv.y; acc[2].z += a2 * wv.z; acc[2].w += a2 * wv.w;
        acc[3].x += a3 * wv.x; acc[3].y += a3 * wv.y; acc[3].z += a3 * wv.z; acc[3].w += a3 * wv.w;
    }
    #pragma unroll
    for (int i = 0; i < 4; i++) {
        int gr = row0 + rb + i;
        if (gr < N) {
            float inv = 1.f / fmaxf(cnt[gr], 1.f);
            float4* po = reinterpret_cast<float4*>(out + (size_t)gr * D + tx * 4);
            float4 s = *po;
            s.x = s.x * inv + acc[i].x;
            s.y = s.y * inv + acc[i].y;
            s.z = s.z * inv + acc[i].z;
            s.w = s.w * inv + acc[i].w;
            *po = s;
        }
    }
}

extern "C" void kernel_launch(void* const* d_in, const int* in_sizes, int n_in,
                              void* d_out, int out_size) {
    const float* user_feat = (const float*)d_in[0];
    const float* item_feat = (const float*)d_in[1];
    const int*   rate_src  = (const int*)d_in[2];
    const int*   rate_dst  = (const int*)d_in[3];
    const int*   rev_src   = (const int*)d_in[4];
    const int*   rev_dst   = (const int*)d_in[5];
    const float* W_rate    = (const float*)d_in[6];
    const float* b_rate    = (const float*)d_in[7];
    const float* W_rev     = (const float*)d_in[8];
    const float* b_rev     = (const float*)d_in[9];
    const float* W_loop    = (const float*)d_in[10];
    const float* h_bias    = (const float*)d_in[11];

    float* out      = (float*)d_out;
    float* out_user = out;                          // [NUSER, 64]
    float* out_item = out + (size_t)NUSER * D;      // [NITEM, 64]

    float *wh_rate, *wh_rev, *cnt_user, *cnt_item;
    cudaGetSymbolAddress((void**)&wh_rate, g_Wh_rate);
    cudaGetSymbolAddress((void**)&wh_rev,  g_Wh_rev);
    cudaGetSymbolAddress((void**)&cnt_user, g_cnt_user);
    cudaGetSymbolAddress((void**)&cnt_item, g_cnt_item);

    const int n4 = (NUSER + NITEM) * D / 4;         // 1,600,000 float4s in d_out
    zero_kernel<<<(n4 + 255) / 256, 256>>>((float4*)out, n4);

    gemm64_kernel<<<(NUSER + 63) / 64, 256>>>(user_feat, W_rate, b_rate, wh_rate, NUSER);
    gemm64_kernel<<<(NITEM + 63) / 64, 256>>>(item_feat, W_rev,  b_rev,  wh_rev,  NITEM);

    const int sthreads = NEDGE * 16;
    scatter_kernel<<<(sthreads + 255) / 256, 256>>>(wh_rate, rate_src, rate_dst,
                                                    out_item, cnt_item, NEDGE);
    scatter_kernel<<<(sthreads + 255) / 256, 256>>>(wh_rev,  rev_src,  rev_dst,
                                                    out_user, cnt_user, NEDGE);

    finalize_kernel<<<(NUSER + 63) / 64, 256>>>(user_feat, W_loop, h_bias, cnt_user,
                                                out_user, NUSER);
    finalize_kernel<<<(NITEM + 63) / 64, 256>>>(item_feat, W_loop, h_bias, cnt_item,
                                                out_item, NITEM);
}

// round 2
// speedup vs baseline: 1.2219x; 1.2219x over previous
#include <cuda_runtime.h>

#define NUSER 50000
#define NITEM 50000
#define NEDGE 1600000
#define D 64

// ---- Scratch (device globals; allocation is forbidden) ----
__device__ int g_deg_item[NITEM];
__device__ int g_deg_user[NUSER];
__device__ int g_off_item[NITEM];
__device__ int g_off_user[NUSER];
__device__ int g_cur_item[NITEM];
__device__ int g_cur_user[NUSER];
__device__ int g_esrc_item[NEDGE];    // user ids, grouped by dst item
__device__ int g_esrc_user[NEDGE];    // item ids, grouped by dst user
__device__ float g_mean_item[NITEM * D];   // mean of user_feat over in-edges
__device__ float g_mean_user[NUSER * D];   // mean of item_feat over in-edges

// ---------------------------------------------------------------------------
// Zero the degree counters.
// ---------------------------------------------------------------------------
__global__ void init_kernel() {
    int i = blockIdx.x * blockDim.x + threadIdx.x;
    if (i < NITEM) g_deg_item[i] = 0;
    if (i < NUSER) g_deg_user[i] = 0;
}

// ---------------------------------------------------------------------------
// Degree histogram for both edge types (int atomics, spread addresses).
// ---------------------------------------------------------------------------
__global__ void hist_kernel(const int* __restrict__ rate_dst,
                            const int* __restrict__ rev_dst) {
    int i = blockIdx.x * blockDim.x + threadIdx.x;
    if (i < NEDGE) {
        atomicAdd(&g_deg_item[__ldg(rate_dst + i)], 1);
        atomicAdd(&g_deg_user[__ldg(rev_dst + i)], 1);
    }
}

// ---------------------------------------------------------------------------
// Exclusive prefix sum over the 50K degree bins. Two independent blocks
// (blockIdx 0 -> item, 1 -> user), 1024 threads, shared carry across tiles.
// ---------------------------------------------------------------------------
__global__ void scan_kernel() {
    const int n = (blockIdx.x == 0) ? NITEM : NUSER;
    const int* deg = (blockIdx.x == 0) ? g_deg_item : g_deg_user;
    int* off = (blockIdx.x == 0) ? g_off_item : g_off_user;
    int* cur = (blockIdx.x == 0) ? g_cur_item : g_cur_user;

    __shared__ int wsum[32];
    __shared__ int carry;
    int tid = threadIdx.x, lane = tid & 31, wid = tid >> 5;
    if (tid == 0) carry = 0;
    __syncthreads();

    for (int base = 0; base < n; base += 1024) {
        int i = base + tid;
        int v = (i < n) ? deg[i] : 0;
        int s = v;
        #pragma unroll
        for (int o = 1; o < 32; o <<= 1) {
            int t = __shfl_up_sync(0xffffffffu, s, o);
            if (lane >= o) s += t;
        }
        if (lane == 31) wsum[wid] = s;
        __syncthreads();
        if (wid == 0) {
            int ws = wsum[lane];
            #pragma unroll
            for (int o = 1; o < 32; o <<= 1) {
                int t = __shfl_up_sync(0xffffffffu, ws, o);
                if (lane >= o) ws += t;
            }
            wsum[lane] = ws;
        }
        __syncthreads();
        int excl = carry + (wid ? wsum[wid - 1] : 0) + s - v;
        if (i < n) { off[i] = excl; cur[i] = excl; }
        __syncthreads();
        if (tid == 0) carry += wsum[31];
        __syncthreads();
    }
}

// ---------------------------------------------------------------------------
// Bin edges by destination: slot = atomic cursor bump, store source id.
// ---------------------------------------------------------------------------
__global__ void bin_kernel(const int* __restrict__ rate_src, const int* __restrict__ rate_dst,
                           const int* __restrict__ rev_src,  const int* __restrict__ rev_dst) {
    int i = blockIdx.x * blockDim.x + threadIdx.x;
    if (i < NEDGE) {
        int p = atomicAdd(&g_cur_item[__ldg(rate_dst + i)], 1);
        g_esrc_item[p] = __ldg(rate_src + i);
        int q = atomicAdd(&g_cur_user[__ldg(rev_dst + i)], 1);
        g_esrc_user[q] = __ldg(rev_src + i);
    }
}

// ---------------------------------------------------------------------------
// Gather-based segment mean: 16 threads per dst node, each owns one float4
// lane of the 64-wide feature. Reads src rows from L2, single write per node.
// ---------------------------------------------------------------------------
__global__ void agg_kernel(const float* __restrict__ feat, const int* __restrict__ esrc,
                           const int* __restrict__ off, const int* __restrict__ deg,
                           float* __restrict__ mean) {
    int t = blockIdx.x * blockDim.x + threadIdx.x;
    int g = t >> 4;          // node id (grid sized exactly: nnode*16 threads)
    int lane = t & 15;
    int dgc = __ldg(deg + g);
    int start = __ldg(off + g);
    float4 acc = make_float4(0.f, 0.f, 0.f, 0.f);
    #pragma unroll 4
    for (int j = 0; j < dgc; j++) {
        int s = __ldg(esrc + start + j);
        float4 v = *reinterpret_cast<const float4*>(feat + (size_t)s * D + lane * 4);
        acc.x += v.x; acc.y += v.y; acc.z += v.z; acc.w += v.w;
    }
    float inv = (dgc > 0) ? 1.f / (float)dgc : 0.f;
    acc.x *= inv; acc.y *= inv; acc.z *= inv; acc.w *= inv;
    *reinterpret_cast<float4*>(mean + (size_t)g * D + lane * 4) = acc;
}

// ---------------------------------------------------------------------------
// Fused dual GEMM finalize:
//   out = feat @ W_loop + mean @ W_et + (deg>0 ? b_et : 0) + h_bias
// 64-row tile, 4x4 register blocking, two accumulate phases over shared tiles.
// ---------------------------------------------------------------------------
__global__ void final_kernel(const float* __restrict__ A0, const float* __restrict__ W0,
                             const float* __restrict__ A1, const float* __restrict__ W1,
                             const float* __restrict__ bet, const float* __restrict__ hb,
                             const int* __restrict__ deg, float* __restrict__ out, int N) {
    __shared__ float As[64][68];
    __shared__ float Ws[64][68];
    __shared__ float bias_h[64];
    __shared__ float bias_e[64];
    const int tid = threadIdx.x;
    const int tx = tid & 15, ty = tid >> 4;
    const int row0 = blockIdx.x * 64;
    const int rb = ty * 4;

    if (tid < 64) bias_h[tid] = hb[tid];
    else if (tid < 128) bias_e[tid - 64] = bet[tid - 64];

    float4 acc[4];
    #pragma unroll
    for (int i = 0; i < 4; i++) acc[i] = make_float4(0.f, 0.f, 0.f, 0.f);

    #pragma unroll
    for (int phase = 0; phase < 2; phase++) {
        const float* A = phase ? A1 : A0;
        const float* W = phase ? W1 : W0;
        __syncthreads();   // protect shared reuse from previous phase
        #pragma unroll
        for (int i = tid; i < 1024; i += 256) {
            int k = i >> 4, c4 = (i & 15) << 2;
            float4 w = *reinterpret_cast<const float4*>(W + k * 64 + c4);
            Ws[k][c4] = w.x; Ws[k][c4 + 1] = w.y; Ws[k][c4 + 2] = w.z; Ws[k][c4 + 3] = w.w;
        }
        #pragma unroll
        for (int i = tid; i < 1024; i += 256) {
            int r = i >> 4, k4 = (i & 15) << 2;
            int gr = row0 + r;
            float4 a = (gr < N) ? *reinterpret_cast<const float4*>(A + (size_t)gr * D + k4)
                                : make_float4(0.f, 0.f, 0.f, 0.f);
            As[r][k4] = a.x; As[r][k4 + 1] = a.y; As[r][k4 + 2] = a.z; As[r][k4 + 3] = a.w;
        }
        __syncthreads();
        #pragma unroll
        for (int k = 0; k < 64; k++) {
            float4 wv = *reinterpret_cast<const float4*>(&Ws[k][tx * 4]);
            float a0 = As[rb + 0][k], a1 = As[rb + 1][k], a2 = As[rb + 2][k], a3 = As[rb + 3][k];
            acc[0].x += a0 * wv.x; acc[0].y += a0 * wv.y; acc[0].z += a0 * wv.z; acc[0].w += a0 * wv.w;
            acc[1].x += a1 * wv.x; acc[1].y += a1 * wv.y; acc[1].z += a1 * wv.z; acc[1].w += a1 * wv.w;
            acc[2].x += a2 * wv.x; acc[2].y += a2 * wv.y; acc[2].z += a2 * wv.z; acc[2].w += a2 * wv.w;
            acc[3].x += a3 * wv.x; acc[3].y += a3 * wv.y; acc[3].z += a3 * wv.z; acc[3].w += a3 * wv.w;
        }
    }

    #pragma unroll
    for (int i = 0; i < 4; i++) {
        int gr = row0 + rb + i;
        if (gr < N) {
            float m = (__ldg(deg + gr) > 0) ? 1.f : 0.f;
            float4 r = acc[i];
            r.x += bias_h[tx * 4 + 0] + m * bias_e[tx * 4 + 0];
            r.y += bias_h[tx * 4 + 1] + m * bias_e[tx * 4 + 1];
            r.z += bias_h[tx * 4 + 2] + m * bias_e[tx * 4 + 2];
            r.w += bias_h[tx * 4 + 3] + m * bias_e[tx * 4 + 3];
            *reinterpret_cast<float4*>(out + (size_t)gr * D + tx * 4) = r;
        }
    }
}

extern "C" void kernel_launch(void* const* d_in, const int* in_sizes, int n_in,
                              void* d_out, int out_size) {
    const float* user_feat = (const float*)d_in[0];
    const float* item_feat = (const float*)d_in[1];
    const int*   rate_src  = (const int*)d_in[2];
    const int*   rate_dst  = (const int*)d_in[3];
    const int*   rev_src   = (const int*)d_in[4];
    const int*   rev_dst   = (const int*)d_in[5];
    const float* W_rate    = (const float*)d_in[6];
    const float* b_rate    = (const float*)d_in[7];
    const float* W_rev     = (const float*)d_in[8];
    const float* b_rev     = (const float*)d_in[9];
    const float* W_loop    = (const float*)d_in[10];
    const float* h_bias    = (const float*)d_in[11];

    float* out      = (float*)d_out;
    float* out_user = out;
    float* out_item = out + (size_t)NUSER * D;

    int *deg_item, *deg_user, *esrc_item, *esrc_user, *off_item, *off_user;
    float *mean_item, *mean_user;
    cudaGetSymbolAddress((void**)&deg_item, g_deg_item);
    cudaGetSymbolAddress((void**)&deg_user, g_deg_user);
    cudaGetSymbolAddress((void**)&off_item, g_off_item);
    cudaGetSymbolAddress((void**)&off_user, g_off_user);
    cudaGetSymbolAddress((void**)&esrc_item, g_esrc_item);
    cudaGetSymbolAddress((void**)&esrc_user, g_esrc_user);
    cudaGetSymbolAddress((void**)&mean_item, g_mean_item);
    cudaGetSymbolAddress((void**)&mean_user, g_mean_user);

    init_kernel<<<(NUSER + 255) / 256, 256>>>();
    hist_kernel<<<(NEDGE + 255) / 256, 256>>>(rate_dst, rev_dst);
    scan_kernel<<<2, 1024>>>();
    bin_kernel<<<(NEDGE + 255) / 256, 256>>>(rate_src, rate_dst, rev_src, rev_dst);

    // item side aggregates USER features; user side aggregates ITEM features.
    agg_kernel<<<NITEM * 16 / 256, 256>>>(user_feat, esrc_item, off_item, deg_item, mean_item);
    agg_kernel<<<NUSER * 16 / 256, 256>>>(item_feat, esrc_user, off_user, deg_user, mean_user);

    final_kernel<<<(NUSER + 63) / 64, 256>>>(user_feat, W_loop, mean_user, W_rev,
                                             b_rev, h_bias, deg_user, out_user, NUSER);
    final_kernel<<<(NITEM + 63) / 64, 256>>>(item_feat, W_loop, mean_item, W_rate,
                                             b_rate, h_bias, deg_item, out_item, NITEM);
}